// round 1
// baseline (speedup 1.0000x reference)
#include <cuda_runtime.h>
#include <math.h>

// Problem constants
#define B_  2
#define S_  2048
#define D_  1024
#define H_  16
#define DK_ 64
#define M_  (B_*S_)   // 4096 rows for the projection GEMMs

// Scratch (device globals — no allocation allowed)
__device__ float g_Qp[B_*S_*D_];
__device__ float g_Kp[B_*S_*D_];
__device__ float g_Vp[B_*S_*D_];
__device__ float g_O [B_*S_*D_];

// ---------------------------------------------------------------------------
// GEMM: Y[M,N] = X[M,K] @ W[N,K]^T + bias[N]
// Tile: BM=128, BN=64, BK=16, 128 threads, 8x8 microtile per thread.
// ---------------------------------------------------------------------------
__global__ __launch_bounds__(128)
void gemm_bias_kernel(const float* __restrict__ X,
                      const float* __restrict__ W,
                      const float* __restrict__ bias,
                      float* __restrict__ Y,
                      int M, int N, int K)
{
    __shared__ float As[16][132];   // [BK][BM+4] (pad keeps 16B row alignment)
    __shared__ float Bs[16][68];    // [BK][BN+4]

    const int tid = threadIdx.x;
    const int m0  = blockIdx.y * 128;
    const int n0  = blockIdx.x * 64;
    const int tm  = tid >> 3;       // 0..15  -> rows tm*8 .. tm*8+7
    const int tn  = tid & 7;        // 0..7   -> cols tn*8 .. tn*8+7

    float acc[8][8];
#pragma unroll
    for (int i = 0; i < 8; i++)
#pragma unroll
        for (int j = 0; j < 8; j++)
            acc[i][j] = 0.f;

    for (int k0 = 0; k0 < K; k0 += 16) {
        // Load A tile: 128 rows x 16 floats (transposed into As[k][m])
#pragma unroll
        for (int p = 0; p < 4; p++) {
            int idx = tid + p * 128;         // 0..511
            int r   = idx >> 2;              // 0..127
            int c   = idx & 3;               // float4 column
            float4 v = *(const float4*)&X[(size_t)(m0 + r) * K + k0 + c * 4];
            As[c*4+0][r] = v.x;
            As[c*4+1][r] = v.y;
            As[c*4+2][r] = v.z;
            As[c*4+3][r] = v.w;
        }
        // Load B tile: 64 rows x 16 floats (transposed into Bs[k][n])
#pragma unroll
        for (int p = 0; p < 2; p++) {
            int idx = tid + p * 128;         // 0..255
            int r   = idx >> 2;              // 0..63
            int c   = idx & 3;
            float4 v = *(const float4*)&W[(size_t)(n0 + r) * K + k0 + c * 4];
            Bs[c*4+0][r] = v.x;
            Bs[c*4+1][r] = v.y;
            Bs[c*4+2][r] = v.z;
            Bs[c*4+3][r] = v.w;
        }
        __syncthreads();

#pragma unroll
        for (int k = 0; k < 16; k++) {
            float a[8], b[8];
            *(float4*)&a[0] = *(const float4*)&As[k][tm * 8];
            *(float4*)&a[4] = *(const float4*)&As[k][tm * 8 + 4];
            *(float4*)&b[0] = *(const float4*)&Bs[k][tn * 8];
            *(float4*)&b[4] = *(const float4*)&Bs[k][tn * 8 + 4];
#pragma unroll
            for (int i = 0; i < 8; i++)
#pragma unroll
                for (int j = 0; j < 8; j++)
                    acc[i][j] = fmaf(a[i], b[j], acc[i][j]);
        }
        __syncthreads();
    }

    // Epilogue: add bias, store
#pragma unroll
    for (int i = 0; i < 8; i++) {
        int m = m0 + tm * 8 + i;
#pragma unroll
        for (int j = 0; j < 8; j += 4) {
            int n = n0 + tn * 8 + j;
            float4 o;
            o.x = acc[i][j+0] + bias[n+0];
            o.y = acc[i][j+1] + bias[n+1];
            o.z = acc[i][j+2] + bias[n+2];
            o.w = acc[i][j+3] + bias[n+3];
            *(float4*)&Y[(size_t)m * N + n] = o;
        }
    }
}

// ---------------------------------------------------------------------------
// Flash attention (causal), fp32.
// Grid: (S/128, B*H). 128 threads/CTA, one query row per thread.
// K/V tiles of 64 keys in smem; online softmax in 8-key subtiles.
// ---------------------------------------------------------------------------
__global__ __launch_bounds__(128)
void flash_attn_kernel(const float* __restrict__ Qp,
                       const float* __restrict__ Kp,
                       const float* __restrict__ Vp,
                       float* __restrict__ O)
{
    __shared__ float Ks[64][64];
    __shared__ float Vs[64][64];

    const int t     = threadIdx.x;
    const int qtile = blockIdx.x;      // 0..15
    const int bh    = blockIdx.y;      // 0..31
    const int b     = bh / H_;
    const int h     = bh % H_;
    const int qi    = qtile * 128 + t; // this thread's query index

    // Load this thread's q row into registers
    const float* qrow = &Qp[((size_t)b * S_ + qi) * D_ + h * DK_];
    float q[64];
#pragma unroll
    for (int d4 = 0; d4 < 16; d4++) {
        float4 v = *(const float4*)&qrow[d4 * 4];
        q[d4*4+0] = v.x; q[d4*4+1] = v.y; q[d4*4+2] = v.z; q[d4*4+3] = v.w;
    }

    float acc[64];
#pragma unroll
    for (int d = 0; d < 64; d++) acc[d] = 0.f;
    float m = -INFINITY;
    float l = 0.f;

    const int ntiles = qtile * 2 + 2;  // causal: only tiles with keys <= max qi
    for (int kt = 0; kt < ntiles; kt++) {
        const int kb = kt * 64;
        // Cooperative load of K and V tiles (64 x 64 floats each)
#pragma unroll
        for (int p = 0; p < 8; p++) {
            int idx = t + p * 128;       // 0..1023
            int r   = idx >> 4;          // 0..63
            int c   = idx & 15;          // float4 col 0..15
            size_t g = ((size_t)b * S_ + kb + r) * D_ + h * DK_ + c * 4;
            *(float4*)&Ks[r][c * 4] = *(const float4*)&Kp[g];
            *(float4*)&Vs[r][c * 4] = *(const float4*)&Vp[g];
        }
        __syncthreads();

        for (int j0 = 0; j0 < 64; j0 += 8) {     // 8-key subtiles (code-size bound)
            float s[8];
#pragma unroll
            for (int jj = 0; jj < 8; jj++) {
                float sj = 0.f;
#pragma unroll
                for (int d4 = 0; d4 < 16; d4++) {
                    float4 kv = *(const float4*)&Ks[j0 + jj][d4 * 4];
                    sj = fmaf(q[d4*4+0], kv.x, sj);
                    sj = fmaf(q[d4*4+1], kv.y, sj);
                    sj = fmaf(q[d4*4+2], kv.z, sj);
                    sj = fmaf(q[d4*4+3], kv.w, sj);
                }
                int kj = kb + j0 + jj;
                s[jj] = (kj <= qi) ? sj * 0.125f : -1e9f;  // match reference mask
            }
            // Online softmax update
            float mt = m;
#pragma unroll
            for (int jj = 0; jj < 8; jj++) mt = fmaxf(mt, s[jj]);
            float scale = __expf(m - mt);
            float p[8];
            float ls = 0.f;
#pragma unroll
            for (int jj = 0; jj < 8; jj++) {
                p[jj] = __expf(s[jj] - mt);
                ls += p[jj];
            }
            l = l * scale + ls;
            m = mt;
#pragma unroll
            for (int d = 0; d < 64; d++) acc[d] *= scale;
            // Accumulate P @ V
#pragma unroll
            for (int jj = 0; jj < 8; jj++) {
                float pj = p[jj];
#pragma unroll
                for (int d4 = 0; d4 < 16; d4++) {
                    float4 vv = *(const float4*)&Vs[j0 + jj][d4 * 4];
                    acc[d4*4+0] = fmaf(pj, vv.x, acc[d4*4+0]);
                    acc[d4*4+1] = fmaf(pj, vv.y, acc[d4*4+1]);
                    acc[d4*4+2] = fmaf(pj, vv.z, acc[d4*4+2]);
                    acc[d4*4+3] = fmaf(pj, vv.w, acc[d4*4+3]);
                }
            }
        }
        __syncthreads();
    }

    const float inv = 1.f / l;
    float* orow = &O[((size_t)b * S_ + qi) * D_ + h * DK_];
#pragma unroll
    for (int d4 = 0; d4 < 16; d4++) {
        float4 o;
        o.x = acc[d4*4+0] * inv;
        o.y = acc[d4*4+1] * inv;
        o.z = acc[d4*4+2] * inv;
        o.w = acc[d4*4+3] * inv;
        *(float4*)&orow[d4 * 4] = o;
    }
}

// ---------------------------------------------------------------------------
// Launch
// Inputs (metadata order): q,k,v,mask,Wq,bq,Wk,bk,Wv,bv,Wo,bo
// ---------------------------------------------------------------------------
extern "C" void kernel_launch(void* const* d_in, const int* in_sizes, int n_in,
                              void* d_out, int out_size)
{
    const float* q    = (const float*)d_in[0];
    const float* k    = (const float*)d_in[1];
    const float* v    = (const float*)d_in[2];
    // d_in[3] = mask (causal, implemented directly)
    const float* Wq   = (const float*)d_in[4];
    const float* bq   = (const float*)d_in[5];
    const float* Wk   = (const float*)d_in[6];
    const float* bk   = (const float*)d_in[7];
    const float* Wv   = (const float*)d_in[8];
    const float* bv   = (const float*)d_in[9];
    const float* Wo   = (const float*)d_in[10];
    const float* bo   = (const float*)d_in[11];
    float* out = (float*)d_out;

    float *Qp, *Kp, *Vp, *O;
    cudaGetSymbolAddress((void**)&Qp, g_Qp);
    cudaGetSymbolAddress((void**)&Kp, g_Kp);
    cudaGetSymbolAddress((void**)&Vp, g_Vp);
    cudaGetSymbolAddress((void**)&O,  g_O);

    dim3 gblk(128);
    dim3 ggrid(D_ / 64, M_ / 128);   // (16, 32)

    gemm_bias_kernel<<<ggrid, gblk>>>(q, Wq, bq, Qp, M_, D_, D_);
    gemm_bias_kernel<<<ggrid, gblk>>>(k, Wk, bk, Kp, M_, D_, D_);
    gemm_bias_kernel<<<ggrid, gblk>>>(v, Wv, bv, Vp, M_, D_, D_);

    dim3 fgrid(S_ / 128, B_ * H_);   // (16, 32)
    flash_attn_kernel<<<fgrid, 128>>>(Qp, Kp, Vp, O);

    gemm_bias_kernel<<<ggrid, gblk>>>(O, Wo, bo, out, M_, D_, D_);
}

// round 4
// speedup vs baseline: 1.1671x; 1.1671x over previous
#include <cuda_runtime.h>
#include <cuda_bf16.h>
#include <cuda_pipeline.h>
#include <mma.h>
#include <math.h>

using namespace nvcuda;

// Problem constants
#define B_  2
#define S_  2048
#define D_  1024
#define H_  16
#define DK_ 64
#define M_  (B_*S_)   // 4096 rows for the projection GEMMs

// GEMM tiling
#define BM 128
#define BN 64
#define BK 16
#define LDT 24          // padded smem row length in elements (48 bytes)

// Scratch (device globals — no allocation allowed)
__device__ float g_Qp[B_*S_*D_];
__device__ float g_Kp[B_*S_*D_];
__device__ float g_Vp[B_*S_*D_];
__device__ float g_O [B_*S_*D_];
// bf16 hi/lo split buffers (reused sequentially across the 4 GEMMs)
__device__ __nv_bfloat16 g_Xh[M_*D_];
__device__ __nv_bfloat16 g_Xl[M_*D_];
__device__ __nv_bfloat16 g_Wh[D_*D_];
__device__ __nv_bfloat16 g_Wl[D_*D_];

// ---------------------------------------------------------------------------
// fp32 -> (hi, lo) bf16 split. x ~= hi + lo with small residual error.
// ---------------------------------------------------------------------------
__global__ __launch_bounds__(256)
void cvt_split_kernel(const float4* __restrict__ x,
                      __nv_bfloat16* __restrict__ hi,
                      __nv_bfloat16* __restrict__ lo,
                      int n4)
{
    int i = blockIdx.x * blockDim.x + threadIdx.x;
    if (i >= n4) return;
    float4 v = x[i];
    __nv_bfloat16 h0 = __float2bfloat16(v.x);
    __nv_bfloat16 h1 = __float2bfloat16(v.y);
    __nv_bfloat16 h2 = __float2bfloat16(v.z);
    __nv_bfloat16 h3 = __float2bfloat16(v.w);
    __nv_bfloat162 hh0, hh1, ll0, ll1;
    hh0.x = h0; hh0.y = h1; hh1.x = h2; hh1.y = h3;
    ll0.x = __float2bfloat16(v.x - __bfloat162float(h0));
    ll0.y = __float2bfloat16(v.y - __bfloat162float(h1));
    ll1.x = __float2bfloat16(v.z - __bfloat162float(h2));
    ll1.y = __float2bfloat16(v.w - __bfloat162float(h3));
    *(__nv_bfloat162*)&hi[i*4]     = hh0;
    *(__nv_bfloat162*)&hi[i*4 + 2] = hh1;
    *(__nv_bfloat162*)&lo[i*4]     = ll0;
    *(__nv_bfloat162*)&lo[i*4 + 2] = ll1;
}

// ---------------------------------------------------------------------------
// Tensor-core GEMM via wmma: Y[M,N] = X[M,K] @ W[N,K]^T + bias[N].
// fp32-accurate via bf16 hi/lo split (3 mma passes).
// CTA tile 128x64, BK=16, double-buffered static smem, 256 threads (8 warps),
// warp tile 32x32 (2x2 m16n16k16 fragments).
// ---------------------------------------------------------------------------
__global__ __launch_bounds__(256)
void gemm_wmma_kernel(const __nv_bfloat16* __restrict__ Xh,
                      const __nv_bfloat16* __restrict__ Xl,
                      const __nv_bfloat16* __restrict__ Wh,
                      const __nv_bfloat16* __restrict__ Wl,
                      const float* __restrict__ bias,
                      float* __restrict__ Y,
                      int M, int N, int K)
{
    __shared__ __align__(16) __nv_bfloat16 sAh[2][BM][LDT];
    __shared__ __align__(16) __nv_bfloat16 sAl[2][BM][LDT];
    __shared__ __align__(16) __nv_bfloat16 sBh[2][BN][LDT];
    __shared__ __align__(16) __nv_bfloat16 sBl[2][BN][LDT];
    __shared__ __align__(16) float biasTile[16][72];

    const int tid = threadIdx.x;
    const int wid = tid >> 5;
    const int m0  = blockIdx.y * BM;
    const int n0  = blockIdx.x * BN;
    const int wm  = (wid & 3) * 32;    // warp M offset within CTA tile
    const int wn  = (wid >> 2) * 32;   // warp N offset within CTA tile

    // Per-thread copy assignments
    const int ra = tid >> 1;           // A row 0..127
    const int ca = tid & 1;            // A 16B chunk 0..1
    const int rb = tid >> 2;           // B row 0..63
    const int qb = tid & 3;
    const int cb = qb & 1;             // B 16B chunk
    const int hb = qb >> 1;            // B hi or lo

    // Bias tile: 16 identical rows of bias[n0..n0+63]
    for (int idx = tid; idx < 16 * 64; idx += 256) {
        int r = idx >> 6;
        int c = idx & 63;
        biasTile[r][c] = bias[n0 + c];
    }
    __syncthreads();

    wmma::fragment<wmma::accumulator, 16, 16, 16, float> acc[2][2];
    for (int mi = 0; mi < 2; mi++)
        for (int ni = 0; ni < 2; ni++)
            wmma::load_matrix_sync(acc[mi][ni], &biasTile[0][wn + ni * 16], 72,
                                   wmma::mem_row_major);

    const int NT = K / BK;   // 64

    // Prologue: prefetch tile 0 into stage 0
    {
        const __nv_bfloat16* srcAh = Xh + (size_t)(m0 + ra) * K + ca * 8;
        const __nv_bfloat16* srcAl = Xl + (size_t)(m0 + ra) * K + ca * 8;
        __pipeline_memcpy_async(&sAh[0][ra][ca * 8], srcAh, 16);
        __pipeline_memcpy_async(&sAl[0][ra][ca * 8], srcAl, 16);
        const __nv_bfloat16* srcB = (hb == 0 ? Wh : Wl) + (size_t)(n0 + rb) * K + cb * 8;
        __nv_bfloat16* dstB = (hb == 0 ? &sBh[0][rb][cb * 8] : &sBl[0][rb][cb * 8]);
        __pipeline_memcpy_async(dstB, srcB, 16);
        __pipeline_commit();
    }

    for (int t = 0; t < NT; t++) {
        int st = t & 1;
        if (t + 1 < NT) {
            int k0 = (t + 1) * BK;
            int sn = (t + 1) & 1;
            const __nv_bfloat16* srcAh = Xh + (size_t)(m0 + ra) * K + k0 + ca * 8;
            const __nv_bfloat16* srcAl = Xl + (size_t)(m0 + ra) * K + k0 + ca * 8;
            __pipeline_memcpy_async(&sAh[sn][ra][ca * 8], srcAh, 16);
            __pipeline_memcpy_async(&sAl[sn][ra][ca * 8], srcAl, 16);
            const __nv_bfloat16* srcB = (hb == 0 ? Wh : Wl) + (size_t)(n0 + rb) * K + k0 + cb * 8;
            __nv_bfloat16* dstB = (hb == 0 ? &sBh[sn][rb][cb * 8] : &sBl[sn][rb][cb * 8]);
            __pipeline_memcpy_async(dstB, srcB, 16);
            __pipeline_commit();
            __pipeline_wait_prior(1);
        } else {
            __pipeline_wait_prior(0);
        }
        __syncthreads();

        wmma::fragment<wmma::matrix_a, 16, 16, 16, __nv_bfloat16, wmma::row_major> ah[2], al[2];
        wmma::fragment<wmma::matrix_b, 16, 16, 16, __nv_bfloat16, wmma::col_major> bh[2], bl[2];
        for (int mi = 0; mi < 2; mi++) {
            wmma::load_matrix_sync(ah[mi], &sAh[st][wm + mi * 16][0], LDT);
            wmma::load_matrix_sync(al[mi], &sAl[st][wm + mi * 16][0], LDT);
        }
        for (int ni = 0; ni < 2; ni++) {
            wmma::load_matrix_sync(bh[ni], &sBh[st][wn + ni * 16][0], LDT);
            wmma::load_matrix_sync(bl[ni], &sBl[st][wn + ni * 16][0], LDT);
        }
        for (int mi = 0; mi < 2; mi++) {
            for (int ni = 0; ni < 2; ni++) {
                wmma::mma_sync(acc[mi][ni], ah[mi], bh[ni], acc[mi][ni]);
                wmma::mma_sync(acc[mi][ni], ah[mi], bl[ni], acc[mi][ni]);
                wmma::mma_sync(acc[mi][ni], al[mi], bh[ni], acc[mi][ni]);
            }
        }
        __syncthreads();
    }

    // Epilogue: store (bias already folded into the initial accumulator)
    for (int mi = 0; mi < 2; mi++) {
        for (int ni = 0; ni < 2; ni++) {
            int row = m0 + wm + mi * 16;
            int col = n0 + wn + ni * 16;
            wmma::store_matrix_sync(&Y[(size_t)row * N + col], acc[mi][ni], N,
                                    wmma::mem_row_major);
        }
    }
}

// ---------------------------------------------------------------------------
// Flash attention (causal), fp32 — unchanged from the passing R1 baseline.
// ---------------------------------------------------------------------------
__global__ __launch_bounds__(128)
void flash_attn_kernel(const float* __restrict__ Qp,
                       const float* __restrict__ Kp,
                       const float* __restrict__ Vp,
                       float* __restrict__ O)
{
    __shared__ float Ks[64][64];
    __shared__ float Vs[64][64];

    const int t     = threadIdx.x;
    const int qtile = blockIdx.x;
    const int bh    = blockIdx.y;
    const int b     = bh / H_;
    const int h     = bh % H_;
    const int qi    = qtile * 128 + t;

    const float* qrow = &Qp[((size_t)b * S_ + qi) * D_ + h * DK_];
    float q[64];
#pragma unroll
    for (int d4 = 0; d4 < 16; d4++) {
        float4 v = *(const float4*)&qrow[d4 * 4];
        q[d4*4+0] = v.x; q[d4*4+1] = v.y; q[d4*4+2] = v.z; q[d4*4+3] = v.w;
    }

    float acc[64];
#pragma unroll
    for (int d = 0; d < 64; d++) acc[d] = 0.f;
    float m = -INFINITY;
    float l = 0.f;

    const int ntiles = qtile * 2 + 2;
    for (int kt = 0; kt < ntiles; kt++) {
        const int kb = kt * 64;
#pragma unroll
        for (int p = 0; p < 8; p++) {
            int idx = t + p * 128;
            int r   = idx >> 4;
            int c   = idx & 15;
            size_t g = ((size_t)b * S_ + kb + r) * D_ + h * DK_ + c * 4;
            *(float4*)&Ks[r][c * 4] = *(const float4*)&Kp[g];
            *(float4*)&Vs[r][c * 4] = *(const float4*)&Vp[g];
        }
        __syncthreads();

        for (int j0 = 0; j0 < 64; j0 += 8) {
            float s[8];
#pragma unroll
            for (int jj = 0; jj < 8; jj++) {
                float sj = 0.f;
#pragma unroll
                for (int d4 = 0; d4 < 16; d4++) {
                    float4 kv = *(const float4*)&Ks[j0 + jj][d4 * 4];
                    sj = fmaf(q[d4*4+0], kv.x, sj);
                    sj = fmaf(q[d4*4+1], kv.y, sj);
                    sj = fmaf(q[d4*4+2], kv.z, sj);
                    sj = fmaf(q[d4*4+3], kv.w, sj);
                }
                int kj = kb + j0 + jj;
                s[jj] = (kj <= qi) ? sj * 0.125f : -1e9f;
            }
            float mt = m;
#pragma unroll
            for (int jj = 0; jj < 8; jj++) mt = fmaxf(mt, s[jj]);
            float scale = __expf(m - mt);
            float p[8];
            float ls = 0.f;
#pragma unroll
            for (int jj = 0; jj < 8; jj++) {
                p[jj] = __expf(s[jj] - mt);
                ls += p[jj];
            }
            l = l * scale + ls;
            m = mt;
#pragma unroll
            for (int d = 0; d < 64; d++) acc[d] *= scale;
#pragma unroll
            for (int jj = 0; jj < 8; jj++) {
                float pj = p[jj];
#pragma unroll
                for (int d4 = 0; d4 < 16; d4++) {
                    float4 vv = *(const float4*)&Vs[j0 + jj][d4 * 4];
                    acc[d4*4+0] = fmaf(pj, vv.x, acc[d4*4+0]);
                    acc[d4*4+1] = fmaf(pj, vv.y, acc[d4*4+1]);
                    acc[d4*4+2] = fmaf(pj, vv.z, acc[d4*4+2]);
                    acc[d4*4+3] = fmaf(pj, vv.w, acc[d4*4+3]);
                }
            }
        }
        __syncthreads();
    }

    const float inv = 1.f / l;
    float* orow = &O[((size_t)b * S_ + qi) * D_ + h * DK_];
#pragma unroll
    for (int d4 = 0; d4 < 16; d4++) {
        float4 o;
        o.x = acc[d4*4+0] * inv;
        o.y = acc[d4*4+1] * inv;
        o.z = acc[d4*4+2] * inv;
        o.w = acc[d4*4+3] * inv;
        *(float4*)&orow[d4 * 4] = o;
    }
}

// ---------------------------------------------------------------------------
// Launch. Inputs: q,k,v,mask,Wq,bq,Wk,bk,Wv,bv,Wo,bo
// ---------------------------------------------------------------------------
extern "C" void kernel_launch(void* const* d_in, const int* in_sizes, int n_in,
                              void* d_out, int out_size)
{
    const float* q    = (const float*)d_in[0];
    const float* k    = (const float*)d_in[1];
    const float* v    = (const float*)d_in[2];
    const float* Wq   = (const float*)d_in[4];
    const float* bq   = (const float*)d_in[5];
    const float* Wk   = (const float*)d_in[6];
    const float* bk   = (const float*)d_in[7];
    const float* Wv   = (const float*)d_in[8];
    const float* bv   = (const float*)d_in[9];
    const float* Wo   = (const float*)d_in[10];
    const float* bo   = (const float*)d_in[11];
    float* out = (float*)d_out;

    float *Qp;
    float *Kp;
    float *Vp;
    float *O;
    __nv_bfloat16 *Xh;
    __nv_bfloat16 *Xl;
    __nv_bfloat16 *Wh;
    __nv_bfloat16 *Wl;
    cudaGetSymbolAddress((void**)&Qp, g_Qp);
    cudaGetSymbolAddress((void**)&Kp, g_Kp);
    cudaGetSymbolAddress((void**)&Vp, g_Vp);
    cudaGetSymbolAddress((void**)&O,  g_O);
    cudaGetSymbolAddress((void**)&Xh, g_Xh);
    cudaGetSymbolAddress((void**)&Xl, g_Xl);
    cudaGetSymbolAddress((void**)&Wh, g_Wh);
    cudaGetSymbolAddress((void**)&Wl, g_Wl);

    const int nX4 = M_ * D_ / 4;
    const int nW4 = D_ * D_ / 4;
    dim3 cvtX((nX4 + 255) / 256);
    dim3 cvtW((nW4 + 255) / 256);
    dim3 ggrid(D_ / BN, M_ / BM);

    // Q projection
    cvt_split_kernel<<<cvtX, 256>>>((const float4*)q,  Xh, Xl, nX4);
    cvt_split_kernel<<<cvtW, 256>>>((const float4*)Wq, Wh, Wl, nW4);
    gemm_wmma_kernel<<<ggrid, 256>>>(Xh, Xl, Wh, Wl, bq, Qp, M_, D_, D_);
    // K projection
    cvt_split_kernel<<<cvtX, 256>>>((const float4*)k,  Xh, Xl, nX4);
    cvt_split_kernel<<<cvtW, 256>>>((const float4*)Wk, Wh, Wl, nW4);
    gemm_wmma_kernel<<<ggrid, 256>>>(Xh, Xl, Wh, Wl, bk, Kp, M_, D_, D_);
    // V projection
    cvt_split_kernel<<<cvtX, 256>>>((const float4*)v,  Xh, Xl, nX4);
    cvt_split_kernel<<<cvtW, 256>>>((const float4*)Wv, Wh, Wl, nW4);
    gemm_wmma_kernel<<<ggrid, 256>>>(Xh, Xl, Wh, Wl, bv, Vp, M_, D_, D_);

    // Attention
    dim3 fgrid(S_ / 128, B_ * H_);
    flash_attn_kernel<<<fgrid, 128>>>(Qp, Kp, Vp, O);

    // Output projection
    cvt_split_kernel<<<cvtX, 256>>>((const float4*)O,  Xh, Xl, nX4);
    cvt_split_kernel<<<cvtW, 256>>>((const float4*)Wo, Wh, Wl, nW4);
    gemm_wmma_kernel<<<ggrid, 256>>>(Xh, Xl, Wh, Wl, bo, out, M_, D_, D_);
}

// round 6
// speedup vs baseline: 1.2028x; 1.0306x over previous
#include <cuda_runtime.h>
#include <cuda_bf16.h>
#include <cuda_pipeline.h>
#include <mma.h>
#include <math.h>

using namespace nvcuda;

// R6 = R5 resubmission: R5 failed with cudaErrorSystemNotReady (802) inside
// harness init (fabric manager not up on a fresh GB300 container) — the
// kernel itself never executed. Source is unchanged.

// Problem constants
#define B_  2
#define S_  2048
#define D_  1024
#define H_  16
#define DK_ 64
#define M_  (B_*S_)

// GEMM tiling
#define BM 128
#define BN 128
#define BK 32
#define LDT 40                    // padded smem row (elements); 80B stride
#define TILE_ELEMS (BM*LDT)       // 5120 elements per tile
#define STAGE_ELEMS (4*TILE_ELEMS)// Ah, Al, Bh, Bl
#define SMEM_BYTES (2*STAGE_ELEMS*2)

// Scratch (device globals — no allocation allowed)
__device__ float g_Qp[B_*S_*D_];
__device__ float g_Kp[B_*S_*D_];
__device__ float g_Vp[B_*S_*D_];
__device__ float g_O [B_*S_*D_];
__device__ __nv_bfloat16 g_Xh[M_*D_];
__device__ __nv_bfloat16 g_Xl[M_*D_];
__device__ __nv_bfloat16 g_Wh[D_*D_];
__device__ __nv_bfloat16 g_Wl[D_*D_];

// ---------------------------------------------------------------------------
// fp32 -> (hi, lo) bf16 split.
// ---------------------------------------------------------------------------
__global__ __launch_bounds__(256)
void cvt_split_kernel(const float4* __restrict__ x,
                      __nv_bfloat16* __restrict__ hi,
                      __nv_bfloat16* __restrict__ lo,
                      int n4)
{
    int i = blockIdx.x * blockDim.x + threadIdx.x;
    if (i >= n4) return;
    float4 v = x[i];
    __nv_bfloat16 h0 = __float2bfloat16(v.x);
    __nv_bfloat16 h1 = __float2bfloat16(v.y);
    __nv_bfloat16 h2 = __float2bfloat16(v.z);
    __nv_bfloat16 h3 = __float2bfloat16(v.w);
    __nv_bfloat162 hh0, hh1, ll0, ll1;
    hh0.x = h0; hh0.y = h1; hh1.x = h2; hh1.y = h3;
    ll0.x = __float2bfloat16(v.x - __bfloat162float(h0));
    ll0.y = __float2bfloat16(v.y - __bfloat162float(h1));
    ll1.x = __float2bfloat16(v.z - __bfloat162float(h2));
    ll1.y = __float2bfloat16(v.w - __bfloat162float(h3));
    *(__nv_bfloat162*)&hi[i*4]     = hh0;
    *(__nv_bfloat162*)&hi[i*4 + 2] = hh1;
    *(__nv_bfloat162*)&lo[i*4]     = ll0;
    *(__nv_bfloat162*)&lo[i*4 + 2] = ll1;
}

// ---------------------------------------------------------------------------
// Tensor-core GEMM v2: Y[M,N] = X[M,K] @ W[N,K]^T + bias[N].
// CTA 128x128, BK=32 double-buffered dynamic smem (80KB), 8 warps,
// warp tile 64x32 -> 48 mma per 24 fragment loads per main-loop iteration.
// ---------------------------------------------------------------------------
__global__ __launch_bounds__(256)
void gemm_wmma_kernel(const __nv_bfloat16* __restrict__ Xh,
                      const __nv_bfloat16* __restrict__ Xl,
                      const __nv_bfloat16* __restrict__ Wh,
                      const __nv_bfloat16* __restrict__ Wl,
                      const float* __restrict__ bias,
                      float* __restrict__ Y,
                      int M, int N, int K)
{
    extern __shared__ __nv_bfloat16 sm[];
    __shared__ __align__(16) float biasTile[16][136];

    const int tid = threadIdx.x;
    const int wid = tid >> 5;
    const int m0  = blockIdx.y * BM;
    const int n0  = blockIdx.x * BN;
    const int wm  = (wid & 1) * 64;    // warp M offset (2 warps in M)
    const int wn  = (wid >> 1) * 32;   // warp N offset (4 warps in N)

    // Bias tile: 16 identical rows of bias[n0..n0+127]
    for (int idx = tid; idx < 16 * 128; idx += 256) {
        int r = idx >> 7;
        int c = idx & 127;
        biasTile[r][c] = bias[n0 + c];
    }
    __syncthreads();

    wmma::fragment<wmma::accumulator, 16, 16, 16, float> acc[4][2];
    for (int mi = 0; mi < 4; mi++)
        for (int ni = 0; ni < 2; ni++)
            wmma::load_matrix_sync(acc[mi][ni], &biasTile[0][wn + ni * 16], 136,
                                   wmma::mem_row_major);

    const int NT = K / BK;   // 32

    // Prologue: prefetch tile 0 into stage 0 (each thread: 8 x 16B)
    {
        for (int p = 0; p < 2; p++) {
            int chunk = tid + p * 256;       // 0..511
            int row = chunk >> 2;
            int cc  = chunk & 3;
            const __nv_bfloat16* sa = Xh + (size_t)(m0 + row) * K + cc * 8;
            const __nv_bfloat16* sb = Xl + (size_t)(m0 + row) * K + cc * 8;
            const __nv_bfloat16* sc = Wh + (size_t)(n0 + row) * K + cc * 8;
            const __nv_bfloat16* sd = Wl + (size_t)(n0 + row) * K + cc * 8;
            int so = row * LDT + cc * 8;
            __pipeline_memcpy_async(&sm[so], sa, 16);
            __pipeline_memcpy_async(&sm[TILE_ELEMS + so], sb, 16);
            __pipeline_memcpy_async(&sm[2 * TILE_ELEMS + so], sc, 16);
            __pipeline_memcpy_async(&sm[3 * TILE_ELEMS + so], sd, 16);
        }
        __pipeline_commit();
    }

    for (int t = 0; t < NT; t++) {
        int st = (t & 1) * STAGE_ELEMS;
        if (t + 1 < NT) {
            int k0 = (t + 1) * BK;
            int sn = ((t + 1) & 1) * STAGE_ELEMS;
            for (int p = 0; p < 2; p++) {
                int chunk = tid + p * 256;
                int row = chunk >> 2;
                int cc  = chunk & 3;
                const __nv_bfloat16* sa = Xh + (size_t)(m0 + row) * K + k0 + cc * 8;
                const __nv_bfloat16* sb = Xl + (size_t)(m0 + row) * K + k0 + cc * 8;
                const __nv_bfloat16* sc = Wh + (size_t)(n0 + row) * K + k0 + cc * 8;
                const __nv_bfloat16* sd = Wl + (size_t)(n0 + row) * K + k0 + cc * 8;
                int so = row * LDT + cc * 8;
                __pipeline_memcpy_async(&sm[sn + so], sa, 16);
                __pipeline_memcpy_async(&sm[sn + TILE_ELEMS + so], sb, 16);
                __pipeline_memcpy_async(&sm[sn + 2 * TILE_ELEMS + so], sc, 16);
                __pipeline_memcpy_async(&sm[sn + 3 * TILE_ELEMS + so], sd, 16);
            }
            __pipeline_commit();
            __pipeline_wait_prior(1);
        } else {
            __pipeline_wait_prior(0);
        }
        __syncthreads();

        for (int ks = 0; ks < 2; ks++) {
            int kc = ks * 16;
            wmma::fragment<wmma::matrix_a, 16, 16, 16, __nv_bfloat16, wmma::row_major> ah[4], al[4];
            wmma::fragment<wmma::matrix_b, 16, 16, 16, __nv_bfloat16, wmma::col_major> bh[2], bl[2];
            for (int mi = 0; mi < 4; mi++) {
                int r = wm + mi * 16;
                wmma::load_matrix_sync(ah[mi], &sm[st + r * LDT + kc], LDT);
                wmma::load_matrix_sync(al[mi], &sm[st + TILE_ELEMS + r * LDT + kc], LDT);
            }
            for (int ni = 0; ni < 2; ni++) {
                int r = wn + ni * 16;
                wmma::load_matrix_sync(bh[ni], &sm[st + 2 * TILE_ELEMS + r * LDT + kc], LDT);
                wmma::load_matrix_sync(bl[ni], &sm[st + 3 * TILE_ELEMS + r * LDT + kc], LDT);
            }
            for (int mi = 0; mi < 4; mi++) {
                for (int ni = 0; ni < 2; ni++) {
                    wmma::mma_sync(acc[mi][ni], ah[mi], bh[ni], acc[mi][ni]);
                    wmma::mma_sync(acc[mi][ni], ah[mi], bl[ni], acc[mi][ni]);
                    wmma::mma_sync(acc[mi][ni], al[mi], bh[ni], acc[mi][ni]);
                }
            }
        }
        __syncthreads();
    }

    for (int mi = 0; mi < 4; mi++) {
        for (int ni = 0; ni < 2; ni++) {
            int row = m0 + wm + mi * 16;
            int col = n0 + wn + ni * 16;
            wmma::store_matrix_sync(&Y[(size_t)row * N + col], acc[mi][ni], N,
                                    wmma::mem_row_major);
        }
    }
}

// ---------------------------------------------------------------------------
// Flash attention v2 (causal), fp32. 256 threads/CTA, 2 threads per query
// (each owns 32 of the 64 dims); score combined via shfl_xor(1).
// Halves register pressure -> 2 CTAs/SM (16 warps vs 4).
// ---------------------------------------------------------------------------
__global__ __launch_bounds__(256)
void flash_attn_kernel(const float* __restrict__ Qp,
                       const float* __restrict__ Kp,
                       const float* __restrict__ Vp,
                       float* __restrict__ O)
{
    __shared__ float Ks[64][64];
    __shared__ float Vs[64][64];

    const int tid   = threadIdx.x;
    const int t     = tid >> 1;        // query slot 0..127
    const int half  = tid & 1;         // which 32-dim half
    const int qtile = blockIdx.x;
    const int bh    = blockIdx.y;
    const int b     = bh / H_;
    const int h     = bh % H_;
    const int qi    = qtile * 128 + t;
    const int hoff  = half * 32;

    const float* qrow = &Qp[((size_t)b * S_ + qi) * D_ + h * DK_ + hoff];
    float q[32];
#pragma unroll
    for (int d4 = 0; d4 < 8; d4++) {
        float4 v = *(const float4*)&qrow[d4 * 4];
        q[d4*4+0] = v.x; q[d4*4+1] = v.y; q[d4*4+2] = v.z; q[d4*4+3] = v.w;
    }

    float acc[32];
#pragma unroll
    for (int d = 0; d < 32; d++) acc[d] = 0.f;
    float m = -INFINITY;
    float l = 0.f;

    const int ntiles = qtile * 2 + 2;
    for (int kt = 0; kt < ntiles; kt++) {
        const int kb = kt * 64;
#pragma unroll
        for (int p = 0; p < 4; p++) {
            int idx = tid + p * 256;
            int r   = idx >> 4;
            int c   = idx & 15;
            size_t g = ((size_t)b * S_ + kb + r) * D_ + h * DK_ + c * 4;
            *(float4*)&Ks[r][c * 4] = *(const float4*)&Kp[g];
            *(float4*)&Vs[r][c * 4] = *(const float4*)&Vp[g];
        }
        __syncthreads();

        for (int j0 = 0; j0 < 64; j0 += 8) {
            float s[8];
#pragma unroll
            for (int jj = 0; jj < 8; jj++) {
                float sj = 0.f;
#pragma unroll
                for (int d4 = 0; d4 < 8; d4++) {
                    float4 kv = *(const float4*)&Ks[j0 + jj][hoff + d4 * 4];
                    sj = fmaf(q[d4*4+0], kv.x, sj);
                    sj = fmaf(q[d4*4+1], kv.y, sj);
                    sj = fmaf(q[d4*4+2], kv.z, sj);
                    sj = fmaf(q[d4*4+3], kv.w, sj);
                }
                sj += __shfl_xor_sync(0xffffffffu, sj, 1);
                int kj = kb + j0 + jj;
                s[jj] = (kj <= qi) ? sj * 0.125f : -1e9f;
            }
            float mt = m;
#pragma unroll
            for (int jj = 0; jj < 8; jj++) mt = fmaxf(mt, s[jj]);
            float scale = __expf(m - mt);
            float p[8];
            float ls = 0.f;
#pragma unroll
            for (int jj = 0; jj < 8; jj++) {
                p[jj] = __expf(s[jj] - mt);
                ls += p[jj];
            }
            l = l * scale + ls;
            m = mt;
#pragma unroll
            for (int d = 0; d < 32; d++) acc[d] *= scale;
#pragma unroll
            for (int jj = 0; jj < 8; jj++) {
                float pj = p[jj];
#pragma unroll
                for (int d4 = 0; d4 < 8; d4++) {
                    float4 vv = *(const float4*)&Vs[j0 + jj][hoff + d4 * 4];
                    acc[d4*4+0] = fmaf(pj, vv.x, acc[d4*4+0]);
                    acc[d4*4+1] = fmaf(pj, vv.y, acc[d4*4+1]);
                    acc[d4*4+2] = fmaf(pj, vv.z, acc[d4*4+2]);
                    acc[d4*4+3] = fmaf(pj, vv.w, acc[d4*4+3]);
                }
            }
        }
        __syncthreads();
    }

    const float inv = 1.f / l;
    float* orow = &O[((size_t)b * S_ + qi) * D_ + h * DK_ + hoff];
#pragma unroll
    for (int d4 = 0; d4 < 8; d4++) {
        float4 o;
        o.x = acc[d4*4+0] * inv;
        o.y = acc[d4*4+1] * inv;
        o.z = acc[d4*4+2] * inv;
        o.w = acc[d4*4+3] * inv;
        *(float4*)&orow[d4 * 4] = o;
    }
}

// ---------------------------------------------------------------------------
// Launch. Inputs: q,k,v,mask,Wq,bq,Wk,bk,Wv,bv,Wo,bo
// ---------------------------------------------------------------------------
extern "C" void kernel_launch(void* const* d_in, const int* in_sizes, int n_in,
                              void* d_out, int out_size)
{
    const float* q    = (const float*)d_in[0];
    const float* k    = (const float*)d_in[1];
    const float* v    = (const float*)d_in[2];
    const float* Wq   = (const float*)d_in[4];
    const float* bq   = (const float*)d_in[5];
    const float* Wk   = (const float*)d_in[6];
    const float* bk   = (const float*)d_in[7];
    const float* Wv   = (const float*)d_in[8];
    const float* bv   = (const float*)d_in[9];
    const float* Wo   = (const float*)d_in[10];
    const float* bo   = (const float*)d_in[11];
    float* out = (float*)d_out;

    float *Qp;
    float *Kp;
    float *Vp;
    float *O;
    __nv_bfloat16 *Xh;
    __nv_bfloat16 *Xl;
    __nv_bfloat16 *Wh;
    __nv_bfloat16 *Wl;
    cudaGetSymbolAddress((void**)&Qp, g_Qp);
    cudaGetSymbolAddress((void**)&Kp, g_Kp);
    cudaGetSymbolAddress((void**)&Vp, g_Vp);
    cudaGetSymbolAddress((void**)&O,  g_O);
    cudaGetSymbolAddress((void**)&Xh, g_Xh);
    cudaGetSymbolAddress((void**)&Xl, g_Xl);
    cudaGetSymbolAddress((void**)&Wh, g_Wh);
    cudaGetSymbolAddress((void**)&Wl, g_Wl);

    cudaFuncSetAttribute(gemm_wmma_kernel,
                         cudaFuncAttributeMaxDynamicSharedMemorySize, SMEM_BYTES);

    const int nX4 = M_ * D_ / 4;
    const int nW4 = D_ * D_ / 4;
    dim3 cvtX((nX4 + 255) / 256);
    dim3 cvtW((nW4 + 255) / 256);
    dim3 ggrid(D_ / BN, M_ / BM);

    // Q projection
    cvt_split_kernel<<<cvtX, 256>>>((const float4*)q,  Xh, Xl, nX4);
    cvt_split_kernel<<<cvtW, 256>>>((const float4*)Wq, Wh, Wl, nW4);
    gemm_wmma_kernel<<<ggrid, 256, SMEM_BYTES>>>(Xh, Xl, Wh, Wl, bq, Qp, M_, D_, D_);
    // K projection
    cvt_split_kernel<<<cvtX, 256>>>((const float4*)k,  Xh, Xl, nX4);
    cvt_split_kernel<<<cvtW, 256>>>((const float4*)Wk, Wh, Wl, nW4);
    gemm_wmma_kernel<<<ggrid, 256, SMEM_BYTES>>>(Xh, Xl, Wh, Wl, bk, Kp, M_, D_, D_);
    // V projection
    cvt_split_kernel<<<cvtX, 256>>>((const float4*)v,  Xh, Xl, nX4);
    cvt_split_kernel<<<cvtW, 256>>>((const float4*)Wv, Wh, Wl, nW4);
    gemm_wmma_kernel<<<ggrid, 256, SMEM_BYTES>>>(Xh, Xl, Wh, Wl, bv, Vp, M_, D_, D_);

    // Attention
    dim3 fgrid(S_ / 128, B_ * H_);
    flash_attn_kernel<<<fgrid, 256>>>(Qp, Kp, Vp, O);

    // Output projection
    cvt_split_kernel<<<cvtX, 256>>>((const float4*)O,  Xh, Xl, nX4);
    cvt_split_kernel<<<cvtW, 256>>>((const float4*)Wo, Wh, Wl, nW4);
    gemm_wmma_kernel<<<ggrid, 256, SMEM_BYTES>>>(Xh, Xl, Wh, Wl, bo, out, M_, D_, D_);
}